// round 4
// baseline (speedup 1.0000x reference)
#include <cuda_runtime.h>
#include <cstdint>

// SpanRepresentation: out[b, span, :] = concat(x[b, start], x[b, end], width_emb[w-1])
//   x: (16, 512, 768) f32, width_emb: (8, 64) f32, L = 512
//   spans: width w=1..8, start s=0..L-w  -> 4068 spans
//   out: (16, 4068, 1600) f32
//
// R3: 256-bit global loads/stores (v8.f32, sm_100+) to halve LSU/L1tex
// instruction pressure; L1 was at 72.8% (co-bottleneck with DRAM 74.6%).

namespace {

constexpr int B  = 16;
constexpr int L  = 512;
constexpr int D  = 768;
constexpr int WD = 64;

// cumulative span offsets per width index wi (0-based)
constexpr int OFF1 = 1 * L - 0;            // 512
constexpr int OFF2 = 2 * L - 1;            // 1023
constexpr int OFF3 = 3 * L - 3;            // 1533
constexpr int OFF4 = 4 * L - 6;            // 2042
constexpr int OFF5 = 5 * L - 10;           // 2550
constexpr int OFF6 = 6 * L - 15;           // 3057
constexpr int OFF7 = 7 * L - 21;           // 3563
constexpr int NSPANS = 8 * L - 28;         // 4068

// 32-byte (8-float) units
constexpr int D8    = D / 8;               // 96 units per x row
constexpr int WD8   = WD / 8;              // 8 units per width_emb row
constexpr int ROW8  = 2 * D8 + WD8;        // 200 units per output row (6400 B)

constexpr int THREADS = 128;

} // namespace

__device__ __forceinline__ void ldg256(const float* p, float4& a, float4& b)
{
    asm("ld.global.nc.v8.f32 {%0,%1,%2,%3,%4,%5,%6,%7}, [%8];"
        : "=f"(a.x), "=f"(a.y), "=f"(a.z), "=f"(a.w),
          "=f"(b.x), "=f"(b.y), "=f"(b.z), "=f"(b.w)
        : "l"(p));
}

__device__ __forceinline__ void stg256(float* p, const float4& a, const float4& b)
{
    asm volatile("st.global.cs.v8.f32 [%0], {%1,%2,%3,%4,%5,%6,%7,%8};"
        :: "l"(p),
           "f"(a.x), "f"(a.y), "f"(a.z), "f"(a.w),
           "f"(b.x), "f"(b.y), "f"(b.z), "f"(b.w)
        : "memory");
}

__global__ __launch_bounds__(THREADS, 16)
void span_repr_kernel(const float* __restrict__ x,
                      const float* __restrict__ wemb,
                      float* __restrict__ out)
{
    const int span = blockIdx.x;       // 0..NSPANS-1
    const int b    = blockIdx.y;       // 0..B-1

    // width index via 7 compares against constexpr cumulative offsets
    int wi = 0;
    if (span >= OFF1) wi = 1;
    if (span >= OFF2) wi = 2;
    if (span >= OFF3) wi = 3;
    if (span >= OFF4) wi = 4;
    if (span >= OFF5) wi = 5;
    if (span >= OFF6) wi = 6;
    if (span >= OFF7) wi = 7;

    int off;
    switch (wi) {
        case 0: off = 0;    break;
        case 1: off = OFF1; break;
        case 2: off = OFF2; break;
        case 3: off = OFF3; break;
        case 4: off = OFF4; break;
        case 5: off = OFF5; break;
        case 6: off = OFF6; break;
        default: off = OFF7; break;
    }
    const int s = span - off;          // start position
    const int e = s + wi;              // end position (= s + w - 1)

    const float* __restrict__ xs = x + (size_t)(b * L + s) * D;
    const float* __restrict__ xe = x + (size_t)(b * L + e) * D;
    const float* __restrict__ we = wemb + wi * WD;
    float*       __restrict__ o  = out + (size_t)(b * NSPANS + span) * (size_t)(ROW8 * 8);

    const int t = threadIdx.x;

    // 200 x 32B units per row; 128 threads -> 2 strided passes (2nd: 72 active)
    #pragma unroll
    for (int j = 0; j < 2; ++j) {
        const int idx = t + j * THREADS;
        float4 a, c;
        if (idx < D8) {
            ldg256(xs + idx * 8, a, c);
            stg256(o + idx * 8, a, c);
        } else if (idx < 2 * D8) {
            ldg256(xe + (idx - D8) * 8, a, c);
            stg256(o + idx * 8, a, c);
        } else if (idx < ROW8) {
            ldg256(we + (idx - 2 * D8) * 8, a, c);
            stg256(o + idx * 8, a, c);
        }
    }
}

extern "C" void kernel_launch(void* const* d_in, const int* in_sizes, int n_in,
                              void* d_out, int out_size)
{
    const float* x    = (const float*)d_in[0];   // (16, 512, 768) f32
    const float* wemb = (const float*)d_in[1];   // (8, 64) f32
    // d_in[2] = batch_max_seq_len (== 512, fixed for this instance) — unused
    float* out = (float*)d_out;

    dim3 grid(NSPANS, B);
    span_repr_kernel<<<grid, THREADS>>>(x, wemb, out);
}

// round 5
// speedup vs baseline: 1.0314x; 1.0314x over previous
#include <cuda_runtime.h>
#include <cstdint>

// SpanRepresentation: out[b, span, :] = concat(x[b, start], x[b, end], width_emb[w-1])
//   x: (16, 512, 768) f32, width_emb: (8, 64) f32, L = 512
//   spans: width w=1..8, start s=0..L-w  -> 4068 spans
//   out: (16, 4068, 1600) f32
//
// R4: back to float4 (R3's 256-bit ld/st was neutral); pack 2 consecutive
// spans per 256-thread CTA (warps 0-3 -> span 2i, warps 4-7 -> span 2i+1)
// to halve block count, keep 12.8KB-contiguous output per CTA, and lift
// achieved occupancy.

namespace {

constexpr int B  = 16;
constexpr int L  = 512;
constexpr int D  = 768;
constexpr int WD = 64;

// cumulative span offsets per width index wi (0-based): off[wi] = wi*L - wi*(wi-1)/2
constexpr int OFF1 = 1 * L - 0;            // 512
constexpr int OFF2 = 2 * L - 1;            // 1023
constexpr int OFF3 = 3 * L - 3;            // 1533
constexpr int OFF4 = 4 * L - 6;            // 2042
constexpr int OFF5 = 5 * L - 10;           // 2550
constexpr int OFF6 = 6 * L - 15;           // 3057
constexpr int OFF7 = 7 * L - 21;           // 3563
constexpr int NSPANS = 8 * L - 28;         // 4068 (even)

constexpr int D4    = D / 4;               // 192 float4 per x row
constexpr int WD4   = WD / 4;              // 16 float4 per width_emb row
constexpr int ROW4  = 2 * D4 + WD4;        // 400 float4 per output row

constexpr int THREADS = 256;               // two 128-thread halves, one span each

} // namespace

__global__ __launch_bounds__(THREADS, 8)
void span_repr_kernel(const float4* __restrict__ x,
                      const float4* __restrict__ wemb,
                      float4* __restrict__ out)
{
    const int half = threadIdx.x >> 7;            // 0 or 1 (warp-aligned split)
    const int t    = threadIdx.x & 127;           // lane within the half
    const int span = blockIdx.x * 2 + half;       // 0..NSPANS-1
    const int b    = blockIdx.y;                  // 0..B-1

    // width index via 7 compares against constexpr cumulative offsets
    int wi = 0;
    if (span >= OFF1) wi = 1;
    if (span >= OFF2) wi = 2;
    if (span >= OFF3) wi = 3;
    if (span >= OFF4) wi = 4;
    if (span >= OFF5) wi = 5;
    if (span >= OFF6) wi = 6;
    if (span >= OFF7) wi = 7;

    int off;
    switch (wi) {
        case 0: off = 0;    break;
        case 1: off = OFF1; break;
        case 2: off = OFF2; break;
        case 3: off = OFF3; break;
        case 4: off = OFF4; break;
        case 5: off = OFF5; break;
        case 6: off = OFF6; break;
        default: off = OFF7; break;
    }
    const int s = span - off;          // start position
    const int e = s + wi;              // end position (= s + w - 1)

    const float4* __restrict__ xs = x + (size_t)(b * L + s) * D4;
    const float4* __restrict__ xe = x + (size_t)(b * L + e) * D4;
    const float4* __restrict__ we = wemb + wi * WD4;
    float4* __restrict__ o = out + (size_t)(b * NSPANS + span) * (size_t)ROW4;

    // 400 float4 per row; 128 threads per half -> 4 strided passes (last partial)
    #pragma unroll
    for (int j = 0; j < 4; ++j) {
        const int idx = t + j * 128;
        if (idx < D4) {
            __stcs(o + idx, __ldg(xs + idx));
        } else if (idx < 2 * D4) {
            __stcs(o + idx, __ldg(xe + (idx - D4)));
        } else if (idx < ROW4) {
            __stcs(o + idx, __ldg(we + (idx - 2 * D4)));
        }
    }
}

extern "C" void kernel_launch(void* const* d_in, const int* in_sizes, int n_in,
                              void* d_out, int out_size)
{
    const float4* x    = (const float4*)d_in[0];   // (16, 512, 768) f32
    const float4* wemb = (const float4*)d_in[1];   // (8, 64) f32
    // d_in[2] = batch_max_seq_len (== 512, fixed for this instance) — unused
    float4* out = (float4*)d_out;

    dim3 grid(NSPANS / 2, B);
    span_repr_kernel<<<grid, THREADS>>>(x, wemb, out);
}